// round 14
// baseline (speedup 1.0000x reference)
#include <cuda_runtime.h>
#include <cuda_bf16.h>
#include <mma.h>
#include <cstdint>

using namespace nvcuda;

#define T_STEPS 512
#define BATCH   64
#define DIN     1024
#define HID     1024
#define N3      3072   // [z | r | c] precomputed x-projections
#define MROWS   (T_STEPS * BATCH)   // 32768

// ---------------- static device scratch (no runtime allocation) ----------------
__device__ float g_P[(size_t)MROWS * N3];               // 384 MB: x-projections (fp32)
__device__ __nv_bfloat16 g_Xh[(size_t)MROWS * DIN];     // X hi (bf16)
__device__ __nv_bfloat16 g_Xl[(size_t)MROWS * DIN];     // X lo
__device__ __nv_bfloat16 g_Bh[(size_t)N3 * DIN];        // phase-1 W rows [n][k] hi
__device__ __nv_bfloat16 g_Bl[(size_t)N3 * DIN];        // phase-1 W rows [n][k] lo
__device__ __nv_bfloat16 g_WAh[2048 * 1024];            // Wfc h-part rows [n][k] hi
__device__ __nv_bfloat16 g_WAl[2048 * 1024];            // lo
__device__ __nv_bfloat16 g_WBh[1024 * 1024];            // Wfc2 h-part rows [n][k] hi
__device__ __nv_bfloat16 g_WBl[1024 * 1024];            // lo
__device__ float g_hb[BATCH * HID];                     // h fp32 (carried state)
__device__ __nv_bfloat16 g_hbh[BATCH * HID];            // h hi
__device__ __nv_bfloat16 g_hbl[BATCH * HID];            // h lo
__device__ float g_PA[4 * BATCH * 2048];                // split-K partials stage A (2MB)
__device__ float g_PB[16 * BATCH * HID];                // split-K partials stage B (4MB)
__device__ unsigned g_bars[16 * 32];                    // 16 barrier counters, 128B apart

// ---------------- init ----------------
__global__ void init_kernel() {
    int i = blockIdx.x * blockDim.x + threadIdx.x;
    if (i < 16 * 32) g_bars[i] = 0u;
    if (i < HID * BATCH) {
        float h0 = 1e-9f;
        g_hb[i] = h0;
        __nv_bfloat16 hh = __float2bfloat16(h0);
        g_hbh[i] = hh;
        g_hbl[i] = __float2bfloat16(h0 - __bfloat162float(hh));
    }
}

// ---------------- convert: fp32 -> bf16 hi/lo for X and all weight views ----------------
__global__ void convert_kernel(const float* __restrict__ x,
                               const float* __restrict__ Wfc,
                               const float* __restrict__ Wfc2) {
    int i = blockIdx.x * blockDim.x + threadIdx.x;
    const size_t NX = (size_t)MROWS * DIN;
    if ((size_t)i < NX) {
        float a = x[i];
        __nv_bfloat16 h = __float2bfloat16(a);
        g_Xh[i] = h;
        g_Xl[i] = __float2bfloat16(a - __bfloat162float(h));
    }
    if (i < N3 * DIN) {            // phase-1 weights: x-part rows
        int n = i >> 10, k = i & 1023;
        float a = (n < 2048) ? Wfc[(size_t)n * 2048 + k]
                             : Wfc2[(size_t)(n - 2048) * 2048 + k];
        __nv_bfloat16 h = __float2bfloat16(a);
        g_Bh[i] = h;
        g_Bl[i] = __float2bfloat16(a - __bfloat162float(h));
    }
    if (i < 2048 * 1024) {         // Wfc h-part rows
        int n = i >> 10, k = i & 1023;
        float a = Wfc[(size_t)n * 2048 + 1024 + k];
        __nv_bfloat16 h = __float2bfloat16(a);
        g_WAh[i] = h;
        g_WAl[i] = __float2bfloat16(a - __bfloat162float(h));
    }
    if (i < 1024 * 1024) {         // Wfc2 h-part rows
        int n = i >> 10, k = i & 1023;
        float a = Wfc2[(size_t)n * 2048 + 1024 + k];
        __nv_bfloat16 h = __float2bfloat16(a);
        g_WBh[i] = h;
        g_WBl[i] = __float2bfloat16(a - __bfloat162float(h));
    }
}

// ---------------- phase 1 (WMMA bf16 hi/lo split): P = X @ W^T ----------------
// 128x128 block tile, 512 threads (16 warps, 32x32 warp tiles).
#define LDT 40

__global__ void __launch_bounds__(512) gemm_p_wmma_kernel() {
    __shared__ __nv_bfloat16 Ah[128][LDT];
    __shared__ __nv_bfloat16 Al[128][LDT];
    __shared__ __nv_bfloat16 Bh[128][LDT];
    __shared__ __nv_bfloat16 Bl[128][LDT];

    const int tid = threadIdx.x, wid = tid >> 5;
    const int m0 = (blockIdx.x / 24) << 7;
    const int n0 = (blockIdx.x % 24) << 7;
    const int wm = (wid >> 2) << 5;   // 0,32,64,96
    const int wn = (wid & 3) << 5;    // 0,32,64,96
    const int lr = tid >> 2, lc = (tid & 3) << 3;   // loader: 1 uint4 per tile

    wmma::fragment<wmma::accumulator, 16, 16, 16, float> acc[2][2];
#pragma unroll
    for (int i = 0; i < 2; i++)
#pragma unroll
        for (int j = 0; j < 2; j++) wmma::fill_fragment(acc[i][j], 0.0f);

    *(uint4*)&Ah[lr][lc] = *(const uint4*)(g_Xh + (size_t)(m0 + lr) * DIN + lc);
    *(uint4*)&Al[lr][lc] = *(const uint4*)(g_Xl + (size_t)(m0 + lr) * DIN + lc);
    *(uint4*)&Bh[lr][lc] = *(const uint4*)(g_Bh + (size_t)(n0 + lr) * DIN + lc);
    *(uint4*)&Bl[lr][lc] = *(const uint4*)(g_Bl + (size_t)(n0 + lr) * DIN + lc);
    __syncthreads();

    for (int k0 = 0; k0 < DIN; k0 += 32) {
        const bool nxt = (k0 + 32) < DIN;
        uint4 pxh, pxl, pwh, pwl;
        if (nxt) {
            pxh = *(const uint4*)(g_Xh + (size_t)(m0 + lr) * DIN + k0 + 32 + lc);
            pxl = *(const uint4*)(g_Xl + (size_t)(m0 + lr) * DIN + k0 + 32 + lc);
            pwh = *(const uint4*)(g_Bh + (size_t)(n0 + lr) * DIN + k0 + 32 + lc);
            pwl = *(const uint4*)(g_Bl + (size_t)(n0 + lr) * DIN + k0 + 32 + lc);
        }
#pragma unroll
        for (int kk = 0; kk < 32; kk += 16) {
            wmma::fragment<wmma::matrix_a, 16, 16, 16, __nv_bfloat16, wmma::row_major> fah[2], fal[2];
            wmma::fragment<wmma::matrix_b, 16, 16, 16, __nv_bfloat16, wmma::col_major> fbh[2], fbl[2];
#pragma unroll
            for (int i = 0; i < 2; i++) {
                wmma::load_matrix_sync(fah[i], &Ah[wm + i * 16][kk], LDT);
                wmma::load_matrix_sync(fal[i], &Al[wm + i * 16][kk], LDT);
            }
#pragma unroll
            for (int j = 0; j < 2; j++) {
                wmma::load_matrix_sync(fbh[j], &Bh[wn + j * 16][kk], LDT);
                wmma::load_matrix_sync(fbl[j], &Bl[wn + j * 16][kk], LDT);
            }
#pragma unroll
            for (int i = 0; i < 2; i++)
#pragma unroll
                for (int j = 0; j < 2; j++) {
                    wmma::mma_sync(acc[i][j], fah[i], fbh[j], acc[i][j]);
                    wmma::mma_sync(acc[i][j], fah[i], fbl[j], acc[i][j]);
                    wmma::mma_sync(acc[i][j], fal[i], fbh[j], acc[i][j]);
                }
        }
        __syncthreads();
        if (nxt) {
            *(uint4*)&Ah[lr][lc] = pxh;
            *(uint4*)&Al[lr][lc] = pxl;
            *(uint4*)&Bh[lr][lc] = pwh;
            *(uint4*)&Bl[lr][lc] = pwl;
            __syncthreads();
        }
    }
#pragma unroll
    for (int i = 0; i < 2; i++)
#pragma unroll
        for (int j = 0; j < 2; j++)
            wmma::store_matrix_sync(
                g_P + (size_t)(m0 + wm + i * 16) * N3 + n0 + wn + j * 16,
                acc[i][j], N3, wmma::mem_row_major);
}

// ---------------- grid barrier: 16-way striped counters + warp-parallel poll ----------------
// Arrivals spread over 16 L2 lines (kills the 27cyc/op same-address atomic convoy);
// warp 0 polls all 16 counters in parallel and warp-reduces the sum.
// release(to any counter) -> acquire(of all counters) preserves visibility.
__device__ __forceinline__ void grid_bar(unsigned target) {
    __syncthreads();                    // block stores happen-before the release
    if (threadIdx.x < 32) {
        if (threadIdx.x == 0) {
            unsigned* ctr = &g_bars[(blockIdx.x & 15) << 5];
            asm volatile("red.release.gpu.add.u32 [%0], %1;" :: "l"(ctr), "r"(1u) : "memory");
        }
        const int lane = threadIdx.x;
        unsigned sum;
        do {
            unsigned v = 0;
            if (lane < 16)
                asm volatile("ld.acquire.gpu.u32 %0, [%1];"
                             : "=r"(v) : "l"(&g_bars[lane << 5]) : "memory");
            sum = v;
#pragma unroll
            for (int o = 16; o; o >>= 1) sum += __shfl_down_sync(0xffffffff, sum, o);
            sum = __shfl_sync(0xffffffff, sum, 0);
        } while (sum < target);
    }
    __syncthreads();                    // broadcast to whole block
}

// ---------------- persistent sequential kernel: weights resident, rebalanced split-K ----------------
// 128 blocks x 512 threads.
// Stage A: 4 kcA x 32 ctA units; out 64x64 @K=256; PA partials = 4.
// Stage B: 16 kcB x 8 ctB units; out 64x128 @K=64; PB partials = 16.
// smem: sWAh/l [64][264], sWBh/l [128][72], sHh/l [64][264]  = 172,032 B.
#define WA_PITCH 264
#define WB_PITCH 72
#define SEQ_SMEM_BYTES (2*64*WA_PITCH*2 + 2*128*WB_PITCH*2 + 2*64*WA_PITCH*2)
#define NBLK 128

__global__ void __launch_bounds__(512, 1) seq_kernel(float* __restrict__ out) {
    extern __shared__ __nv_bfloat16 smem[];
    __nv_bfloat16* sWAh = smem;
    __nv_bfloat16* sWAl = sWAh + 64 * WA_PITCH;
    __nv_bfloat16* sWBh = sWAl + 64 * WA_PITCH;
    __nv_bfloat16* sWBl = sWBh + 128 * WB_PITCH;
    __nv_bfloat16* sHh  = sWBl + 128 * WB_PITCH;
    __nv_bfloat16* sHl  = sHh  + 64 * WA_PITCH;

    const int tid = threadIdx.x, bid = blockIdx.x;
    const int wid = tid >> 5;
    const int gtid = bid * 512 + tid;          // 0..65535 == BATCH*HID
    const int wm  = (wid >> 2) << 4;   // rows: 0,16,32,48
    const int wnA = (wid & 3) << 4;    // stage-A cols: 0,16,32,48
    const int wnB = (wid & 3) << 5;    // stage-B cols: 0,32,64,96
    unsigned bar_t = 0;

    const int kcA = bid >> 5, ctA = bid & 31;      // stage-A unit
    const int k0A = kcA << 8, n0A = ctA << 6;
    const int kcB = bid >> 3, ctB = bid & 7;       // stage-B unit
    const int ks0B = kcB << 6, n0B = ctB << 7;

    // ---- one-time weight preload ----
    for (int u = tid; u < 2048; u += 512) {        // WA: 64 rows x 256 k, hi/lo
        int r = u >> 5, c8 = (u & 31) << 3;
        *(uint4*)&sWAh[r * WA_PITCH + c8] =
            *(const uint4*)(g_WAh + (size_t)(n0A + r) * 1024 + k0A + c8);
        *(uint4*)&sWAl[r * WA_PITCH + c8] =
            *(const uint4*)(g_WAl + (size_t)(n0A + r) * 1024 + k0A + c8);
    }
    for (int u = tid; u < 1024; u += 512) {        // WB: 128 rows x 64 k, hi/lo
        int r = u >> 3, c8 = (u & 7) << 3;
        *(uint4*)&sWBh[r * WB_PITCH + c8] =
            *(const uint4*)(g_WBh + (size_t)(n0B + r) * 1024 + ks0B + c8);
        *(uint4*)&sWBl[r * WB_PITCH + c8] =
            *(const uint4*)(g_WBl + (size_t)(n0B + r) * 1024 + ks0B + c8);
    }
    __syncthreads();

    for (int t = 0; t < T_STEPS; t++) {
        const float* Pt = g_P + (size_t)t * (BATCH * N3);

        // ======== stage A: PA[kcA] slice = h @ WA^T   (64x64 @K=256, weights resident)
        {
            for (int i = tid; i < 2048; i += 512) {    // h slice 64x256 hi/lo
                int r = i >> 5, c8 = (i & 31) << 3;
                *(uint4*)&sHh[r * WA_PITCH + c8] =
                    __ldcg((const uint4*)(g_hbh + (size_t)r * HID + k0A + c8));
                *(uint4*)&sHl[r * WA_PITCH + c8] =
                    __ldcg((const uint4*)(g_hbl + (size_t)r * HID + k0A + c8));
            }
            __syncthreads();

            wmma::fragment<wmma::accumulator, 16, 16, 16, float> acc;
            wmma::fill_fragment(acc, 0.0f);
#pragma unroll
            for (int kk = 0; kk < 256; kk += 16) {
                wmma::fragment<wmma::matrix_a, 16, 16, 16, __nv_bfloat16, wmma::row_major> fah, fal;
                wmma::fragment<wmma::matrix_b, 16, 16, 16, __nv_bfloat16, wmma::col_major> fbh, fbl;
                wmma::load_matrix_sync(fah, sHh + wm * WA_PITCH + kk, WA_PITCH);
                wmma::load_matrix_sync(fal, sHl + wm * WA_PITCH + kk, WA_PITCH);
                wmma::load_matrix_sync(fbh, sWAh + wnA * WA_PITCH + kk, WA_PITCH);
                wmma::load_matrix_sync(fbl, sWAl + wnA * WA_PITCH + kk, WA_PITCH);
                wmma::mma_sync(acc, fah, fbh, acc);
                wmma::mma_sync(acc, fah, fbl, acc);
                wmma::mma_sync(acc, fal, fbh, acc);
            }
            wmma::store_matrix_sync(
                g_PA + (size_t)kcA * (BATCH * 2048) + (size_t)wm * 2048 + n0A + wnA,
                acc, 2048, wmma::mem_row_major);
        }
        bar_t += NBLK; grid_bar(bar_t);

        // ======== stage B: fused r-reduce + (r*h) @ WB^T   (64x128 @K=64, weights resident)
        {
            for (int idx = tid; idx < 4096; idx += 512) {
                int kl = idx & 63, b = idx >> 6;
                int k = ks0B + kl;
                float s = Pt[b * N3 + 1024 + k];
#pragma unroll
                for (int c = 0; c < 4; c++)
                    s += __ldcg(&g_PA[c * (BATCH * 2048) + b * 2048 + 1024 + k]);
                float r = 1.0f / (1.0f + __expf(-s));
                float rh = r * __ldcg(&g_hb[(b << 10) + k]);
                __nv_bfloat16 hi = __float2bfloat16(rh);
                sHh[b * WA_PITCH + kl] = hi;
                sHl[b * WA_PITCH + kl] = __float2bfloat16(rh - __bfloat162float(hi));
            }
            __syncthreads();

            wmma::fragment<wmma::accumulator, 16, 16, 16, float> acc[2];
            wmma::fill_fragment(acc[0], 0.0f);
            wmma::fill_fragment(acc[1], 0.0f);
#pragma unroll
            for (int kk = 0; kk < 64; kk += 16) {
                wmma::fragment<wmma::matrix_a, 16, 16, 16, __nv_bfloat16, wmma::row_major> fah, fal;
                wmma::fragment<wmma::matrix_b, 16, 16, 16, __nv_bfloat16, wmma::col_major> fbh[2], fbl[2];
                wmma::load_matrix_sync(fah, sHh + wm * WA_PITCH + kk, WA_PITCH);
                wmma::load_matrix_sync(fal, sHl + wm * WA_PITCH + kk, WA_PITCH);
#pragma unroll
                for (int j = 0; j < 2; j++) {
                    wmma::load_matrix_sync(fbh[j], sWBh + (wnB + j * 16) * WB_PITCH + kk, WB_PITCH);
                    wmma::load_matrix_sync(fbl[j], sWBl + (wnB + j * 16) * WB_PITCH + kk, WB_PITCH);
                }
#pragma unroll
                for (int j = 0; j < 2; j++) {
                    wmma::mma_sync(acc[j], fah, fbh[j], acc[j]);
                    wmma::mma_sync(acc[j], fah, fbl[j], acc[j]);
                    wmma::mma_sync(acc[j], fal, fbh[j], acc[j]);
                }
            }
#pragma unroll
            for (int j = 0; j < 2; j++)
                wmma::store_matrix_sync(
                    g_PB + (size_t)kcB * (BATCH * 1024) + (size_t)wm * 1024 + n0B + wnB + j * 16,
                    acc[j], 1024, wmma::mem_row_major);
        }
        bar_t += NBLK; grid_bar(bar_t);

        // ======== stage C: z reduce + tanh(c) + blend + h update (+ bf16 mirror) + output
        {
            const int o = gtid;                 // one element per thread
            int b = o >> 10, j = o & 1023;
            float sz = Pt[b * N3 + j];
#pragma unroll
            for (int c = 0; c < 4; c++)
                sz += __ldcg(&g_PA[c * (BATCH * 2048) + b * 2048 + j]);
            float z = 1.0f / (1.0f + __expf(-sz));

            float sc = Pt[b * N3 + 2048 + j];
#pragma unroll
            for (int c = 0; c < 16; c++)
                sc += __ldcg(&g_PB[c * (BATCH * 1024) + o]);
            float cv = tanhf(sc);

            float hcur = __ldcg(&g_hb[o]);
            float hn = fmaf(z, cv - hcur, hcur);   // (1-z)*h + z*c
            out[(size_t)t * (BATCH * HID) + o] = hn;
            g_hb[o] = hn;
            __nv_bfloat16 hh = __float2bfloat16(hn);
            g_hbh[o] = hh;
            g_hbl[o] = __float2bfloat16(hn - __bfloat162float(hh));
        }
        bar_t += NBLK; grid_bar(bar_t);
    }
}

// ---------------- launch (4 graph nodes total) ----------------
extern "C" void kernel_launch(void* const* d_in, const int* in_sizes, int n_in,
                              void* d_out, int out_size) {
    const float* x    = (const float*)d_in[0];   // [512, 64, 1024]
    const float* Wfc  = (const float*)d_in[1];   // [2048, 2048]
    const float* Wfc2 = (const float*)d_in[2];   // [1024, 2048]
    // d_in[3] (w_hh), d_in[4] (bias): dead — delta_u never reaches the output
    float* out = (float*)d_out;                  // [512, 64, 1024]

    // One-time dynamic-smem opt-in; never executed during graph capture.
    static bool attr_done = false;
    if (!attr_done) {
        cudaFuncSetAttribute(seq_kernel,
                             cudaFuncAttributeMaxDynamicSharedMemorySize, SEQ_SMEM_BYTES);
        attr_done = true;
    }

    init_kernel<<<256, 256>>>();
    convert_kernel<<<(MROWS * DIN + 255) / 256, 256>>>(x, Wfc, Wfc2);
    gemm_p_wmma_kernel<<<(MROWS / 128) * (N3 / 128), 512>>>();
    seq_kernel<<<NBLK, 512, SEQ_SMEM_BYTES>>>(out);
}

// round 16
// speedup vs baseline: 1.0220x; 1.0220x over previous
#include <cuda_runtime.h>
#include <cuda_bf16.h>
#include <mma.h>
#include <cstdint>

using namespace nvcuda;

#define T_STEPS 512
#define BATCH   64
#define DIN     1024
#define HID     1024
#define N3      3072   // [z | r | c] precomputed x-projections
#define MROWS   (T_STEPS * BATCH)   // 32768

// ---------------- static device scratch (no runtime allocation) ----------------
__device__ float g_P[(size_t)MROWS * N3];               // 384 MB: x-projections (fp32)
__device__ __nv_bfloat16 g_Xh[(size_t)MROWS * DIN];     // X hi (bf16)
__device__ __nv_bfloat16 g_Xl[(size_t)MROWS * DIN];     // X lo
__device__ __nv_bfloat16 g_Bh[(size_t)N3 * DIN];        // phase-1 W rows [n][k] hi
__device__ __nv_bfloat16 g_Bl[(size_t)N3 * DIN];        // phase-1 W rows [n][k] lo
__device__ __nv_bfloat16 g_WAh[2048 * 1024];            // Wfc h-part rows [n][k] hi
__device__ __nv_bfloat16 g_WAl[2048 * 1024];            // lo
__device__ __nv_bfloat16 g_WBh[1024 * 1024];            // Wfc2 h-part rows [n][k] hi
__device__ __nv_bfloat16 g_WBl[1024 * 1024];            // lo
__device__ float g_hb[BATCH * HID];                     // h fp32 (carried state)
__device__ __nv_bfloat16 g_hbh[BATCH * HID];            // h hi
__device__ __nv_bfloat16 g_hbl[BATCH * HID];            // h lo
__device__ float g_PA[4 * BATCH * 2048];                // split-K partials stage A (2MB)
__device__ float g_PB[16 * BATCH * HID];                // split-K partials stage B (4MB)
__device__ unsigned g_bars[16 * 32];                    // 16 barrier counters, 128B apart

// ---------------- init ----------------
__global__ void init_kernel() {
    int i = blockIdx.x * blockDim.x + threadIdx.x;
    if (i < 16 * 32) g_bars[i] = 0u;
    if (i < HID * BATCH) {
        float h0 = 1e-9f;
        g_hb[i] = h0;
        __nv_bfloat16 hh = __float2bfloat16(h0);
        g_hbh[i] = hh;
        g_hbl[i] = __float2bfloat16(h0 - __bfloat162float(hh));
    }
}

// ---------------- convert: fp32 -> bf16 hi/lo for X and all weight views ----------------
__global__ void convert_kernel(const float* __restrict__ x,
                               const float* __restrict__ Wfc,
                               const float* __restrict__ Wfc2) {
    int i = blockIdx.x * blockDim.x + threadIdx.x;
    const size_t NX = (size_t)MROWS * DIN;
    if ((size_t)i < NX) {
        float a = x[i];
        __nv_bfloat16 h = __float2bfloat16(a);
        g_Xh[i] = h;
        g_Xl[i] = __float2bfloat16(a - __bfloat162float(h));
    }
    if (i < N3 * DIN) {            // phase-1 weights: x-part rows
        int n = i >> 10, k = i & 1023;
        float a = (n < 2048) ? Wfc[(size_t)n * 2048 + k]
                             : Wfc2[(size_t)(n - 2048) * 2048 + k];
        __nv_bfloat16 h = __float2bfloat16(a);
        g_Bh[i] = h;
        g_Bl[i] = __float2bfloat16(a - __bfloat162float(h));
    }
    if (i < 2048 * 1024) {         // Wfc h-part rows
        int n = i >> 10, k = i & 1023;
        float a = Wfc[(size_t)n * 2048 + 1024 + k];
        __nv_bfloat16 h = __float2bfloat16(a);
        g_WAh[i] = h;
        g_WAl[i] = __float2bfloat16(a - __bfloat162float(h));
    }
    if (i < 1024 * 1024) {         // Wfc2 h-part rows
        int n = i >> 10, k = i & 1023;
        float a = Wfc2[(size_t)n * 2048 + 1024 + k];
        __nv_bfloat16 h = __float2bfloat16(a);
        g_WBh[i] = h;
        g_WBl[i] = __float2bfloat16(a - __bfloat162float(h));
    }
}

// ---------------- phase 1 (WMMA bf16 hi/lo split): P = X @ W^T ----------------
// 128x128 block tile, 512 threads (16 warps, 32x32 warp tiles).
#define LDT 40

__global__ void __launch_bounds__(512) gemm_p_wmma_kernel() {
    __shared__ __nv_bfloat16 Ah[128][LDT];
    __shared__ __nv_bfloat16 Al[128][LDT];
    __shared__ __nv_bfloat16 Bh[128][LDT];
    __shared__ __nv_bfloat16 Bl[128][LDT];

    const int tid = threadIdx.x, wid = tid >> 5;
    const int m0 = (blockIdx.x / 24) << 7;
    const int n0 = (blockIdx.x % 24) << 7;
    const int wm = (wid >> 2) << 5;   // 0,32,64,96
    const int wn = (wid & 3) << 5;    // 0,32,64,96
    const int lr = tid >> 2, lc = (tid & 3) << 3;   // loader: 1 uint4 per tile

    wmma::fragment<wmma::accumulator, 16, 16, 16, float> acc[2][2];
#pragma unroll
    for (int i = 0; i < 2; i++)
#pragma unroll
        for (int j = 0; j < 2; j++) wmma::fill_fragment(acc[i][j], 0.0f);

    *(uint4*)&Ah[lr][lc] = *(const uint4*)(g_Xh + (size_t)(m0 + lr) * DIN + lc);
    *(uint4*)&Al[lr][lc] = *(const uint4*)(g_Xl + (size_t)(m0 + lr) * DIN + lc);
    *(uint4*)&Bh[lr][lc] = *(const uint4*)(g_Bh + (size_t)(n0 + lr) * DIN + lc);
    *(uint4*)&Bl[lr][lc] = *(const uint4*)(g_Bl + (size_t)(n0 + lr) * DIN + lc);
    __syncthreads();

    for (int k0 = 0; k0 < DIN; k0 += 32) {
        const bool nxt = (k0 + 32) < DIN;
        uint4 pxh, pxl, pwh, pwl;
        if (nxt) {
            pxh = *(const uint4*)(g_Xh + (size_t)(m0 + lr) * DIN + k0 + 32 + lc);
            pxl = *(const uint4*)(g_Xl + (size_t)(m0 + lr) * DIN + k0 + 32 + lc);
            pwh = *(const uint4*)(g_Bh + (size_t)(n0 + lr) * DIN + k0 + 32 + lc);
            pwl = *(const uint4*)(g_Bl + (size_t)(n0 + lr) * DIN + k0 + 32 + lc);
        }
#pragma unroll
        for (int kk = 0; kk < 32; kk += 16) {
            wmma::fragment<wmma::matrix_a, 16, 16, 16, __nv_bfloat16, wmma::row_major> fah[2], fal[2];
            wmma::fragment<wmma::matrix_b, 16, 16, 16, __nv_bfloat16, wmma::col_major> fbh[2], fbl[2];
#pragma unroll
            for (int i = 0; i < 2; i++) {
                wmma::load_matrix_sync(fah[i], &Ah[wm + i * 16][kk], LDT);
                wmma::load_matrix_sync(fal[i], &Al[wm + i * 16][kk], LDT);
            }
#pragma unroll
            for (int j = 0; j < 2; j++) {
                wmma::load_matrix_sync(fbh[j], &Bh[wn + j * 16][kk], LDT);
                wmma::load_matrix_sync(fbl[j], &Bl[wn + j * 16][kk], LDT);
            }
#pragma unroll
            for (int i = 0; i < 2; i++)
#pragma unroll
                for (int j = 0; j < 2; j++) {
                    wmma::mma_sync(acc[i][j], fah[i], fbh[j], acc[i][j]);
                    wmma::mma_sync(acc[i][j], fah[i], fbl[j], acc[i][j]);
                    wmma::mma_sync(acc[i][j], fal[i], fbh[j], acc[i][j]);
                }
        }
        __syncthreads();
        if (nxt) {
            *(uint4*)&Ah[lr][lc] = pxh;
            *(uint4*)&Al[lr][lc] = pxl;
            *(uint4*)&Bh[lr][lc] = pwh;
            *(uint4*)&Bl[lr][lc] = pwl;
            __syncthreads();
        }
    }
#pragma unroll
    for (int i = 0; i < 2; i++)
#pragma unroll
        for (int j = 0; j < 2; j++)
            wmma::store_matrix_sync(
                g_P + (size_t)(m0 + wm + i * 16) * N3 + n0 + wn + j * 16,
                acc[i][j], N3, wmma::mem_row_major);
}

// ---------------- grid barrier: striped counters + warp-parallel poll ----------------
__device__ __forceinline__ void grid_bar(unsigned target) {
    __syncthreads();                    // block stores happen-before the release
    if (threadIdx.x < 32) {
        if (threadIdx.x == 0) {
            unsigned* ctr = &g_bars[(blockIdx.x & 15) << 5];
            asm volatile("red.release.gpu.add.u32 [%0], %1;" :: "l"(ctr), "r"(1u) : "memory");
        }
        const int lane = threadIdx.x;
        unsigned sum;
        do {
            unsigned v = 0;
            if (lane < 16)
                asm volatile("ld.acquire.gpu.u32 %0, [%1];"
                             : "=r"(v) : "l"(&g_bars[lane << 5]) : "memory");
            sum = v;
#pragma unroll
            for (int o = 16; o; o >>= 1) sum += __shfl_down_sync(0xffffffff, sum, o);
            sum = __shfl_sync(0xffffffff, sum, 0);
        } while (sum < target);
    }
    __syncthreads();                    // broadcast to whole block
}

// ---------------- persistent sequential kernel: weights resident + step-start prefetch ----------------
// 128 blocks x 512 threads.
// Stage A: 4 kcA x 32 ctA units; out 64x64 @K=256; PA partials = 4.
// Stage B: 16 kcB x 8 ctB units; out 64x128 @K=64; PB partials = 16.
// Step-start-available operands of stages B/C (immutable g_P; h(t-1)) are
// prefetched into registers before stage A so their L2 latency hides under
// the MMA pipeline. h tile: each thread owns 32 cols -> 4 uint4 per hi/lo plane.
#define WA_PITCH 264
#define WB_PITCH 72
#define SEQ_SMEM_BYTES (2*64*WA_PITCH*2 + 2*128*WB_PITCH*2 + 2*64*WA_PITCH*2)
#define NBLK 128

__global__ void __launch_bounds__(512, 1) seq_kernel(float* __restrict__ out) {
    extern __shared__ __nv_bfloat16 smem[];
    __nv_bfloat16* sWAh = smem;
    __nv_bfloat16* sWAl = sWAh + 64 * WA_PITCH;
    __nv_bfloat16* sWBh = sWAl + 64 * WA_PITCH;
    __nv_bfloat16* sWBl = sWBh + 128 * WB_PITCH;
    __nv_bfloat16* sHh  = sWBl + 128 * WB_PITCH;
    __nv_bfloat16* sHl  = sHh  + 64 * WA_PITCH;

    const int tid = threadIdx.x, bid = blockIdx.x;
    const int wid = tid >> 5;
    const int gtid = bid * 512 + tid;          // 0..65535 == BATCH*HID
    const int wm  = (wid >> 2) << 4;   // rows: 0,16,32,48
    const int wnA = (wid & 3) << 4;    // stage-A cols: 0,16,32,48
    const int wnB = (wid & 3) << 5;    // stage-B cols: 0,32,64,96
    unsigned bar_t = 0;

    const int kcA = bid >> 5, ctA = bid & 31;      // stage-A unit
    const int k0A = kcA << 8, n0A = ctA << 6;
    const int kcB = bid >> 3, ctB = bid & 7;       // stage-B unit
    const int ks0B = kcB << 6, n0B = ctB << 7;

    // stage-C coords (fixed per thread)
    const int bC = gtid >> 10, jC = gtid & 1023;
    // h-tile loader coords: 8 threads per row, 32 cols (4 uint4) each per plane
    const int hr = tid >> 3, hc = (tid & 7) << 5;

    // ---- one-time weight preload ----
    for (int u = tid; u < 2048; u += 512) {        // WA: 64 rows x 256 k, hi/lo
        int r = u >> 5, c8 = (u & 31) << 3;
        *(uint4*)&sWAh[r * WA_PITCH + c8] =
            *(const uint4*)(g_WAh + (size_t)(n0A + r) * 1024 + k0A + c8);
        *(uint4*)&sWAl[r * WA_PITCH + c8] =
            *(const uint4*)(g_WAl + (size_t)(n0A + r) * 1024 + k0A + c8);
    }
    for (int u = tid; u < 1024; u += 512) {        // WB: 128 rows x 64 k, hi/lo
        int r = u >> 3, c8 = (u & 7) << 3;
        *(uint4*)&sWBh[r * WB_PITCH + c8] =
            *(const uint4*)(g_WBh + (size_t)(n0B + r) * 1024 + ks0B + c8);
        *(uint4*)&sWBl[r * WB_PITCH + c8] =
            *(const uint4*)(g_WBl + (size_t)(n0B + r) * 1024 + ks0B + c8);
    }
    __syncthreads();

    for (int t = 0; t < T_STEPS; t++) {
        const float* Pt = g_P + (size_t)t * (BATCH * N3);

        // ======== step-start: issue stage-A h tile loads + prefetch all
        // step-start-available operands of stages B and C.
        uint4 hv[8];
#pragma unroll
        for (int q = 0; q < 4; q++) {
            hv[q]     = __ldcg((const uint4*)(g_hbh + (size_t)hr * HID + k0A + hc + q * 8));
            hv[4 + q] = __ldcg((const uint4*)(g_hbl + (size_t)hr * HID + k0A + hc + q * 8));
        }
        float prP[8], prH[8];                                   // stage-B prologue operands
#pragma unroll
        for (int i = 0; i < 8; i++) {
            int idx = tid + (i << 9);
            int kl = idx & 63, b = idx >> 6;
            prP[i] = __ldcg(&Pt[b * N3 + 1024 + ks0B + kl]);
            prH[i] = __ldcg(&g_hb[(b << 10) + ks0B + kl]);
        }
        float pz = __ldcg(&Pt[bC * N3 + jC]);                   // stage-C operands
        float pc = __ldcg(&Pt[bC * N3 + 2048 + jC]);
        float phc = __ldcg(&g_hb[gtid]);

        // ======== stage A: PA[kcA] slice = h @ WA^T   (64x64 @K=256, weights resident)
        {
#pragma unroll
            for (int q = 0; q < 4; q++) {
                *(uint4*)&sHh[hr * WA_PITCH + hc + q * 8] = hv[q];
                *(uint4*)&sHl[hr * WA_PITCH + hc + q * 8] = hv[4 + q];
            }
            __syncthreads();

            wmma::fragment<wmma::accumulator, 16, 16, 16, float> acc;
            wmma::fill_fragment(acc, 0.0f);
#pragma unroll
            for (int kk = 0; kk < 256; kk += 16) {
                wmma::fragment<wmma::matrix_a, 16, 16, 16, __nv_bfloat16, wmma::row_major> fah, fal;
                wmma::fragment<wmma::matrix_b, 16, 16, 16, __nv_bfloat16, wmma::col_major> fbh, fbl;
                wmma::load_matrix_sync(fah, sHh + wm * WA_PITCH + kk, WA_PITCH);
                wmma::load_matrix_sync(fal, sHl + wm * WA_PITCH + kk, WA_PITCH);
                wmma::load_matrix_sync(fbh, sWAh + wnA * WA_PITCH + kk, WA_PITCH);
                wmma::load_matrix_sync(fbl, sWAl + wnA * WA_PITCH + kk, WA_PITCH);
                wmma::mma_sync(acc, fah, fbh, acc);
                wmma::mma_sync(acc, fah, fbl, acc);
                wmma::mma_sync(acc, fal, fbh, acc);
            }
            wmma::store_matrix_sync(
                g_PA + (size_t)kcA * (BATCH * 2048) + (size_t)wm * 2048 + n0A + wnA,
                acc, 2048, wmma::mem_row_major);
        }
        bar_t += NBLK; grid_bar(bar_t);

        // ======== stage B: fused r-reduce + (r*h) @ WB^T   (64x128 @K=64, weights resident)
        {
#pragma unroll
            for (int i = 0; i < 8; i++) {
                int idx = tid + (i << 9);
                int kl = idx & 63, b = idx >> 6;
                int k = ks0B + kl;
                float s = prP[i];
#pragma unroll
                for (int c = 0; c < 4; c++)
                    s += __ldcg(&g_PA[c * (BATCH * 2048) + b * 2048 + 1024 + k]);
                float r = 1.0f / (1.0f + __expf(-s));
                float rh = r * prH[i];
                __nv_bfloat16 hi = __float2bfloat16(rh);
                sHh[b * WA_PITCH + kl] = hi;
                sHl[b * WA_PITCH + kl] = __float2bfloat16(rh - __bfloat162float(hi));
            }
            __syncthreads();

            wmma::fragment<wmma::accumulator, 16, 16, 16, float> acc[2];
            wmma::fill_fragment(acc[0], 0.0f);
            wmma::fill_fragment(acc[1], 0.0f);
#pragma unroll
            for (int kk = 0; kk < 64; kk += 16) {
                wmma::fragment<wmma::matrix_a, 16, 16, 16, __nv_bfloat16, wmma::row_major> fah, fal;
                wmma::fragment<wmma::matrix_b, 16, 16, 16, __nv_bfloat16, wmma::col_major> fbh[2], fbl[2];
                wmma::load_matrix_sync(fah, sHh + wm * WA_PITCH + kk, WA_PITCH);
                wmma::load_matrix_sync(fal, sHl + wm * WA_PITCH + kk, WA_PITCH);
#pragma unroll
                for (int j = 0; j < 2; j++) {
                    wmma::load_matrix_sync(fbh[j], sWBh + (wnB + j * 16) * WB_PITCH + kk, WB_PITCH);
                    wmma::load_matrix_sync(fbl[j], sWBl + (wnB + j * 16) * WB_PITCH + kk, WB_PITCH);
                }
#pragma unroll
                for (int j = 0; j < 2; j++) {
                    wmma::mma_sync(acc[j], fah, fbh[j], acc[j]);
                    wmma::mma_sync(acc[j], fah, fbl[j], acc[j]);
                    wmma::mma_sync(acc[j], fal, fbh[j], acc[j]);
                }
            }
#pragma unroll
            for (int j = 0; j < 2; j++)
                wmma::store_matrix_sync(
                    g_PB + (size_t)kcB * (BATCH * 1024) + (size_t)wm * 1024 + n0B + wnB + j * 16,
                    acc[j], 1024, wmma::mem_row_major);
        }
        bar_t += NBLK; grid_bar(bar_t);

        // ======== stage C: z reduce + tanh(c) + blend + h update (+ bf16 mirror) + output
        {
            const int o = gtid;                 // one element per thread
            float sz = pz;
#pragma unroll
            for (int c = 0; c < 4; c++)
                sz += __ldcg(&g_PA[c * (BATCH * 2048) + bC * 2048 + jC]);
            float z = 1.0f / (1.0f + __expf(-sz));

            float sc = pc;
#pragma unroll
            for (int c = 0; c < 16; c++)
                sc += __ldcg(&g_PB[c * (BATCH * 1024) + o]);
            float cv = tanhf(sc);

            float hn = fmaf(z, cv - phc, phc);   // (1-z)*h + z*c
            out[(size_t)t * (BATCH * HID) + o] = hn;
            g_hb[o] = hn;
            __nv_bfloat16 hh = __float2bfloat16(hn);
            g_hbh[o] = hh;
            g_hbl[o] = __float2bfloat16(hn - __bfloat162float(hh));
        }
        bar_t += NBLK; grid_bar(bar_t);
    }
}

// ---------------- launch (4 graph nodes total) ----------------
extern "C" void kernel_launch(void* const* d_in, const int* in_sizes, int n_in,
                              void* d_out, int out_size) {
    const float* x    = (const float*)d_in[0];   // [512, 64, 1024]
    const float* Wfc  = (const float*)d_in[1];   // [2048, 2048]
    const float* Wfc2 = (const float*)d_in[2];   // [1024, 2048]
    // d_in[3] (w_hh), d_in[4] (bias): dead — delta_u never reaches the output
    float* out = (float*)d_out;                  // [512, 64, 1024]

    // One-time dynamic-smem opt-in; never executed during graph capture.
    static bool attr_done = false;
    if (!attr_done) {
        cudaFuncSetAttribute(seq_kernel,
                             cudaFuncAttributeMaxDynamicSharedMemorySize, SEQ_SMEM_BYTES);
        attr_done = true;
    }

    init_kernel<<<256, 256>>>();
    convert_kernel<<<(MROWS * DIN + 255) / 256, 256>>>(x, Wfc, Wfc2);
    gemm_p_wmma_kernel<<<(MROWS / 128) * (N3 / 128), 512>>>();
    seq_kernel<<<NBLK, 512, SEQ_SMEM_BYTES>>>(out);
}

// round 17
// speedup vs baseline: 1.0303x; 1.0082x over previous
#include <cuda_runtime.h>
#include <cuda_bf16.h>
#include <mma.h>
#include <cstdint>

using namespace nvcuda;

#define T_STEPS 512
#define BATCH   64
#define DIN     1024
#define HID     1024
#define N3      3072   // [z | r | c] precomputed x-projections
#define MROWS   (T_STEPS * BATCH)   // 32768

// ---------------- static device scratch (no runtime allocation) ----------------
__device__ float g_P[(size_t)MROWS * N3];               // 384 MB: x-projections (fp32)
__device__ __nv_bfloat16 g_Xh[(size_t)MROWS * DIN];     // X hi (bf16)
__device__ __nv_bfloat16 g_Xl[(size_t)MROWS * DIN];     // X lo
__device__ __nv_bfloat16 g_Bh[(size_t)N3 * DIN];        // phase-1 W rows [n][k] hi
__device__ __nv_bfloat16 g_Bl[(size_t)N3 * DIN];        // phase-1 W rows [n][k] lo
__device__ __nv_bfloat16 g_WAh[2048 * 1024];            // Wfc h-part rows [n][k] hi
__device__ __nv_bfloat16 g_WAl[2048 * 1024];            // lo
__device__ __nv_bfloat16 g_WBh[1024 * 1024];            // Wfc2 h-part rows [n][k] hi
__device__ __nv_bfloat16 g_WBl[1024 * 1024];            // lo
__device__ float g_hb[BATCH * HID];                     // h fp32 (carried state)
__device__ __nv_bfloat16 g_hbh[BATCH * HID];            // h hi
__device__ __nv_bfloat16 g_hbl[BATCH * HID];            // h lo
__device__ float g_PA[4 * BATCH * 2048];                // split-K partials stage A (2MB)
__device__ float g_PB[16 * BATCH * HID];                // split-K partials stage B (4MB)
__device__ unsigned g_bars[16 * 32];                    // 16 barrier counters, 128B apart

// ---------------- init ----------------
__global__ void init_kernel() {
    int i = blockIdx.x * blockDim.x + threadIdx.x;
    if (i < 16 * 32) g_bars[i] = 0u;
    if (i < HID * BATCH) {
        float h0 = 1e-9f;
        g_hb[i] = h0;
        __nv_bfloat16 hh = __float2bfloat16(h0);
        g_hbh[i] = hh;
        g_hbl[i] = __float2bfloat16(h0 - __bfloat162float(hh));
    }
}

// ---------------- convert: fp32 -> bf16 hi/lo for X and all weight views ----------------
__global__ void convert_kernel(const float* __restrict__ x,
                               const float* __restrict__ Wfc,
                               const float* __restrict__ Wfc2) {
    int i = blockIdx.x * blockDim.x + threadIdx.x;
    const size_t NX = (size_t)MROWS * DIN;
    if ((size_t)i < NX) {
        float a = x[i];
        __nv_bfloat16 h = __float2bfloat16(a);
        g_Xh[i] = h;
        g_Xl[i] = __float2bfloat16(a - __bfloat162float(h));
    }
    if (i < N3 * DIN) {            // phase-1 weights: x-part rows
        int n = i >> 10, k = i & 1023;
        float a = (n < 2048) ? Wfc[(size_t)n * 2048 + k]
                             : Wfc2[(size_t)(n - 2048) * 2048 + k];
        __nv_bfloat16 h = __float2bfloat16(a);
        g_Bh[i] = h;
        g_Bl[i] = __float2bfloat16(a - __bfloat162float(h));
    }
    if (i < 2048 * 1024) {         // Wfc h-part rows
        int n = i >> 10, k = i & 1023;
        float a = Wfc[(size_t)n * 2048 + 1024 + k];
        __nv_bfloat16 h = __float2bfloat16(a);
        g_WAh[i] = h;
        g_WAl[i] = __float2bfloat16(a - __bfloat162float(h));
    }
    if (i < 1024 * 1024) {         // Wfc2 h-part rows
        int n = i >> 10, k = i & 1023;
        float a = Wfc2[(size_t)n * 2048 + 1024 + k];
        __nv_bfloat16 h = __float2bfloat16(a);
        g_WBh[i] = h;
        g_WBl[i] = __float2bfloat16(a - __bfloat162float(h));
    }
}

// ---------------- phase 1 (WMMA bf16 hi/lo split): P = X @ W^T ----------------
// 128x128 block tile, 512 threads (16 warps, 32x32 warp tiles).
#define LDT 40

__global__ void __launch_bounds__(512) gemm_p_wmma_kernel() {
    __shared__ __nv_bfloat16 Ah[128][LDT];
    __shared__ __nv_bfloat16 Al[128][LDT];
    __shared__ __nv_bfloat16 Bh[128][LDT];
    __shared__ __nv_bfloat16 Bl[128][LDT];

    const int tid = threadIdx.x, wid = tid >> 5;
    const int m0 = (blockIdx.x / 24) << 7;
    const int n0 = (blockIdx.x % 24) << 7;
    const int wm = (wid >> 2) << 5;   // 0,32,64,96
    const int wn = (wid & 3) << 5;    // 0,32,64,96
    const int lr = tid >> 2, lc = (tid & 3) << 3;   // loader: 1 uint4 per tile

    wmma::fragment<wmma::accumulator, 16, 16, 16, float> acc[2][2];
#pragma unroll
    for (int i = 0; i < 2; i++)
#pragma unroll
        for (int j = 0; j < 2; j++) wmma::fill_fragment(acc[i][j], 0.0f);

    *(uint4*)&Ah[lr][lc] = *(const uint4*)(g_Xh + (size_t)(m0 + lr) * DIN + lc);
    *(uint4*)&Al[lr][lc] = *(const uint4*)(g_Xl + (size_t)(m0 + lr) * DIN + lc);
    *(uint4*)&Bh[lr][lc] = *(const uint4*)(g_Bh + (size_t)(n0 + lr) * DIN + lc);
    *(uint4*)&Bl[lr][lc] = *(const uint4*)(g_Bl + (size_t)(n0 + lr) * DIN + lc);
    __syncthreads();

    for (int k0 = 0; k0 < DIN; k0 += 32) {
        const bool nxt = (k0 + 32) < DIN;
        uint4 pxh, pxl, pwh, pwl;
        if (nxt) {
            pxh = *(const uint4*)(g_Xh + (size_t)(m0 + lr) * DIN + k0 + 32 + lc);
            pxl = *(const uint4*)(g_Xl + (size_t)(m0 + lr) * DIN + k0 + 32 + lc);
            pwh = *(const uint4*)(g_Bh + (size_t)(n0 + lr) * DIN + k0 + 32 + lc);
            pwl = *(const uint4*)(g_Bl + (size_t)(n0 + lr) * DIN + k0 + 32 + lc);
        }
#pragma unroll
        for (int kk = 0; kk < 32; kk += 16) {
            wmma::fragment<wmma::matrix_a, 16, 16, 16, __nv_bfloat16, wmma::row_major> fah[2], fal[2];
            wmma::fragment<wmma::matrix_b, 16, 16, 16, __nv_bfloat16, wmma::col_major> fbh[2], fbl[2];
#pragma unroll
            for (int i = 0; i < 2; i++) {
                wmma::load_matrix_sync(fah[i], &Ah[wm + i * 16][kk], LDT);
                wmma::load_matrix_sync(fal[i], &Al[wm + i * 16][kk], LDT);
            }
#pragma unroll
            for (int j = 0; j < 2; j++) {
                wmma::load_matrix_sync(fbh[j], &Bh[wn + j * 16][kk], LDT);
                wmma::load_matrix_sync(fbl[j], &Bl[wn + j * 16][kk], LDT);
            }
#pragma unroll
            for (int i = 0; i < 2; i++)
#pragma unroll
                for (int j = 0; j < 2; j++) {
                    wmma::mma_sync(acc[i][j], fah[i], fbh[j], acc[i][j]);
                    wmma::mma_sync(acc[i][j], fah[i], fbl[j], acc[i][j]);
                    wmma::mma_sync(acc[i][j], fal[i], fbh[j], acc[i][j]);
                }
        }
        __syncthreads();
        if (nxt) {
            *(uint4*)&Ah[lr][lc] = pxh;
            *(uint4*)&Al[lr][lc] = pxl;
            *(uint4*)&Bh[lr][lc] = pwh;
            *(uint4*)&Bl[lr][lc] = pwl;
            __syncthreads();
        }
    }
#pragma unroll
    for (int i = 0; i < 2; i++)
#pragma unroll
        for (int j = 0; j < 2; j++)
            wmma::store_matrix_sync(
                g_P + (size_t)(m0 + wm + i * 16) * N3 + n0 + wn + j * 16,
                acc[i][j], N3, wmma::mem_row_major);
}

// ---------------- grid barrier: striped counters + warp-parallel poll ----------------
__device__ __forceinline__ void grid_bar(unsigned target) {
    __syncthreads();                    // block stores happen-before the release
    if (threadIdx.x < 32) {
        if (threadIdx.x == 0) {
            unsigned* ctr = &g_bars[(blockIdx.x & 15) << 5];
            asm volatile("red.release.gpu.add.u32 [%0], %1;" :: "l"(ctr), "r"(1u) : "memory");
        }
        const int lane = threadIdx.x;
        unsigned sum;
        do {
            unsigned v = 0;
            if (lane < 16)
                asm volatile("ld.acquire.gpu.u32 %0, [%1];"
                             : "=r"(v) : "l"(&g_bars[lane << 5]) : "memory");
            sum = v;
#pragma unroll
            for (int o = 16; o; o >>= 1) sum += __shfl_down_sync(0xffffffff, sum, o);
            sum = __shfl_sync(0xffffffff, sum, 0);
        } while (sum < target);
    }
    __syncthreads();                    // broadcast to whole block
}

// ---------------- persistent sequential kernel: weights resident + step-start prefetch ----------------
// 128 blocks x 512 threads.
// Stage A: 4 kcA x 32 ctA units; out 64x64 @K=256; PA partials = 4.
// Stage B: 16 kcB x 8 ctB units; out 64x128 @K=64; PB partials = 16.
// Step-start-available operands of stages B/C (immutable g_P; h(t-1)) are
// prefetched into registers before stage A so their L2 latency hides under
// the MMA pipeline. h tile: each thread owns 32 cols -> 4 uint4 per hi/lo plane.
#define WA_PITCH 264
#define WB_PITCH 72
#define SEQ_SMEM_BYTES (2*64*WA_PITCH*2 + 2*128*WB_PITCH*2 + 2*64*WA_PITCH*2)
#define NBLK 128

__global__ void __launch_bounds__(512, 1) seq_kernel(float* __restrict__ out) {
    extern __shared__ __nv_bfloat16 smem[];
    __nv_bfloat16* sWAh = smem;
    __nv_bfloat16* sWAl = sWAh + 64 * WA_PITCH;
    __nv_bfloat16* sWBh = sWAl + 64 * WA_PITCH;
    __nv_bfloat16* sWBl = sWBh + 128 * WB_PITCH;
    __nv_bfloat16* sHh  = sWBl + 128 * WB_PITCH;
    __nv_bfloat16* sHl  = sHh  + 64 * WA_PITCH;

    const int tid = threadIdx.x, bid = blockIdx.x;
    const int wid = tid >> 5;
    const int gtid = bid * 512 + tid;          // 0..65535 == BATCH*HID
    const int wm  = (wid >> 2) << 4;   // rows: 0,16,32,48
    const int wnA = (wid & 3) << 4;    // stage-A cols: 0,16,32,48
    const int wnB = (wid & 3) << 5;    // stage-B cols: 0,32,64,96
    unsigned bar_t = 0;

    const int kcA = bid >> 5, ctA = bid & 31;      // stage-A unit
    const int k0A = kcA << 8, n0A = ctA << 6;
    const int kcB = bid >> 3, ctB = bid & 7;       // stage-B unit
    const int ks0B = kcB << 6, n0B = ctB << 7;

    // stage-C coords (fixed per thread)
    const int bC = gtid >> 10, jC = gtid & 1023;
    // h-tile loader coords: 8 threads per row, 32 cols (4 uint4) each per plane
    const int hr = tid >> 3, hc = (tid & 7) << 5;

    // ---- one-time weight preload ----
    for (int u = tid; u < 2048; u += 512) {        // WA: 64 rows x 256 k, hi/lo
        int r = u >> 5, c8 = (u & 31) << 3;
        *(uint4*)&sWAh[r * WA_PITCH + c8] =
            *(const uint4*)(g_WAh + (size_t)(n0A + r) * 1024 + k0A + c8);
        *(uint4*)&sWAl[r * WA_PITCH + c8] =
            *(const uint4*)(g_WAl + (size_t)(n0A + r) * 1024 + k0A + c8);
    }
    for (int u = tid; u < 1024; u += 512) {        // WB: 128 rows x 64 k, hi/lo
        int r = u >> 3, c8 = (u & 7) << 3;
        *(uint4*)&sWBh[r * WB_PITCH + c8] =
            *(const uint4*)(g_WBh + (size_t)(n0B + r) * 1024 + ks0B + c8);
        *(uint4*)&sWBl[r * WB_PITCH + c8] =
            *(const uint4*)(g_WBl + (size_t)(n0B + r) * 1024 + ks0B + c8);
    }
    __syncthreads();

    for (int t = 0; t < T_STEPS; t++) {
        const float* Pt = g_P + (size_t)t * (BATCH * N3);

        // ======== step-start: issue stage-A h tile loads + prefetch all
        // step-start-available operands of stages B and C.
        uint4 hv[8];
#pragma unroll
        for (int q = 0; q < 4; q++) {
            hv[q]     = __ldcg((const uint4*)(g_hbh + (size_t)hr * HID + k0A + hc + q * 8));
            hv[4 + q] = __ldcg((const uint4*)(g_hbl + (size_t)hr * HID + k0A + hc + q * 8));
        }
        float prP[8], prH[8];                                   // stage-B prologue operands
#pragma unroll
        for (int i = 0; i < 8; i++) {
            int idx = tid + (i << 9);
            int kl = idx & 63, b = idx >> 6;
            prP[i] = __ldcg(&Pt[b * N3 + 1024 + ks0B + kl]);
            prH[i] = __ldcg(&g_hb[(b << 10) + ks0B + kl]);
        }
        float pz = __ldcg(&Pt[bC * N3 + jC]);                   // stage-C operands
        float pc = __ldcg(&Pt[bC * N3 + 2048 + jC]);
        float phc = __ldcg(&g_hb[gtid]);

        // ======== stage A: PA[kcA] slice = h @ WA^T   (64x64 @K=256, weights resident)
        {
#pragma unroll
            for (int q = 0; q < 4; q++) {
                *(uint4*)&sHh[hr * WA_PITCH + hc + q * 8] = hv[q];
                *(uint4*)&sHl[hr * WA_PITCH + hc + q * 8] = hv[4 + q];
            }
            __syncthreads();

            wmma::fragment<wmma::accumulator, 16, 16, 16, float> acc;
            wmma::fill_fragment(acc, 0.0f);
#pragma unroll
            for (int kk = 0; kk < 256; kk += 16) {
                wmma::fragment<wmma::matrix_a, 16, 16, 16, __nv_bfloat16, wmma::row_major> fah, fal;
                wmma::fragment<wmma::matrix_b, 16, 16, 16, __nv_bfloat16, wmma::col_major> fbh, fbl;
                wmma::load_matrix_sync(fah, sHh + wm * WA_PITCH + kk, WA_PITCH);
                wmma::load_matrix_sync(fal, sHl + wm * WA_PITCH + kk, WA_PITCH);
                wmma::load_matrix_sync(fbh, sWAh + wnA * WA_PITCH + kk, WA_PITCH);
                wmma::load_matrix_sync(fbl, sWAl + wnA * WA_PITCH + kk, WA_PITCH);
                wmma::mma_sync(acc, fah, fbh, acc);
                wmma::mma_sync(acc, fah, fbl, acc);
                wmma::mma_sync(acc, fal, fbh, acc);
            }
            wmma::store_matrix_sync(
                g_PA + (size_t)kcA * (BATCH * 2048) + (size_t)wm * 2048 + n0A + wnA,
                acc, 2048, wmma::mem_row_major);
        }
        bar_t += NBLK; grid_bar(bar_t);

        // ======== stage B: fused r-reduce + (r*h) @ WB^T   (64x128 @K=64, weights resident)
        {
#pragma unroll
            for (int i = 0; i < 8; i++) {
                int idx = tid + (i << 9);
                int kl = idx & 63, b = idx >> 6;
                int k = ks0B + kl;
                float s = prP[i];
#pragma unroll
                for (int c = 0; c < 4; c++)
                    s += __ldcg(&g_PA[c * (BATCH * 2048) + b * 2048 + 1024 + k]);
                float r = 1.0f / (1.0f + __expf(-s));
                float rh = r * prH[i];
                __nv_bfloat16 hi = __float2bfloat16(rh);
                sHh[b * WA_PITCH + kl] = hi;
                sHl[b * WA_PITCH + kl] = __float2bfloat16(rh - __bfloat162float(hi));
            }
            __syncthreads();

            wmma::fragment<wmma::accumulator, 16, 16, 16, float> acc[2];
            wmma::fill_fragment(acc[0], 0.0f);
            wmma::fill_fragment(acc[1], 0.0f);
#pragma unroll
            for (int kk = 0; kk < 64; kk += 16) {
                wmma::fragment<wmma::matrix_a, 16, 16, 16, __nv_bfloat16, wmma::row_major> fah, fal;
                wmma::fragment<wmma::matrix_b, 16, 16, 16, __nv_bfloat16, wmma::col_major> fbh[2], fbl[2];
                wmma::load_matrix_sync(fah, sHh + wm * WA_PITCH + kk, WA_PITCH);
                wmma::load_matrix_sync(fal, sHl + wm * WA_PITCH + kk, WA_PITCH);
#pragma unroll
                for (int j = 0; j < 2; j++) {
                    wmma::load_matrix_sync(fbh[j], sWBh + (wnB + j * 16) * WB_PITCH + kk, WB_PITCH);
                    wmma::load_matrix_sync(fbl[j], sWBl + (wnB + j * 16) * WB_PITCH + kk, WB_PITCH);
                }
#pragma unroll
                for (int j = 0; j < 2; j++) {
                    wmma::mma_sync(acc[j], fah, fbh[j], acc[j]);
                    wmma::mma_sync(acc[j], fah, fbl[j], acc[j]);
                    wmma::mma_sync(acc[j], fal, fbh[j], acc[j]);
                }
            }
#pragma unroll
            for (int j = 0; j < 2; j++)
                wmma::store_matrix_sync(
                    g_PB + (size_t)kcB * (BATCH * 1024) + (size_t)wm * 1024 + n0B + wnB + j * 16,
                    acc[j], 1024, wmma::mem_row_major);
        }
        bar_t += NBLK; grid_bar(bar_t);

        // ======== stage C: z reduce + tanh(c) + blend + h update (+ bf16 mirror) + output
        {
            const int o = gtid;                 // one element per thread
            float sz = pz;
#pragma unroll
            for (int c = 0; c < 4; c++)
                sz += __ldcg(&g_PA[c * (BATCH * 2048) + bC * 2048 + jC]);
            float z = 1.0f / (1.0f + __expf(-sz));

            float sc = pc;
#pragma unroll
            for (int c = 0; c < 16; c++)
                sc += __ldcg(&g_PB[c * (BATCH * 1024) + o]);
            float cv = tanhf(sc);

            float hn = fmaf(z, cv - phc, phc);   // (1-z)*h + z*c
            out[(size_t)t * (BATCH * HID) + o] = hn;
            g_hb[o] = hn;
            __nv_bfloat16 hh = __float2bfloat16(hn);
            g_hbh[o] = hh;
            g_hbl[o] = __float2bfloat16(hn - __bfloat162float(hh));
        }
        bar_t += NBLK; grid_bar(bar_t);
    }
}

// ---------------- launch (4 graph nodes total) ----------------
extern "C" void kernel_launch(void* const* d_in, const int* in_sizes, int n_in,
                              void* d_out, int out_size) {
    const float* x    = (const float*)d_in[0];   // [512, 64, 1024]
    const float* Wfc  = (const float*)d_in[1];   // [2048, 2048]
    const float* Wfc2 = (const float*)d_in[2];   // [1024, 2048]
    // d_in[3] (w_hh), d_in[4] (bias): dead — delta_u never reaches the output
    float* out = (float*)d_out;                  // [512, 64, 1024]

    // One-time dynamic-smem opt-in; never executed during graph capture.
    static bool attr_done = false;
    if (!attr_done) {
        cudaFuncSetAttribute(seq_kernel,
                             cudaFuncAttributeMaxDynamicSharedMemorySize, SEQ_SMEM_BYTES);
        attr_done = true;
    }

    init_kernel<<<256, 256>>>();
    convert_kernel<<<(MROWS * DIN + 255) / 256, 256>>>(x, Wfc, Wfc2);
    gemm_p_wmma_kernel<<<(MROWS / 128) * (N3 / 128), 512>>>();
    seq_kernel<<<NBLK, 512, SEQ_SMEM_BYTES>>>(out);
}